// round 11
// baseline (speedup 1.0000x reference)
#include <cuda_runtime.h>

#define NV   8192
#define FEAT 256
#define HIDD 64
#define ALPHA_S 0.2f
#define JSPLIT 4
#define JCHUNK (NV / JSPLIT)   // 2048

// Scratch (device globals: no allocation allowed)
__device__ float g_h[NV * HIDD];                 // 2 MB
__device__ float g_ssrc[NV];
__device__ float g_sdst[NV];
__device__ float g_acc[JSPLIT][NV * HIDD];       // 8 MB partial accumulators
__device__ float g_l[JSPLIT][NV];                // partial softmax denominators

// ---------------- packed f32x2 helpers (Blackwell FFMA2) ----------------
__device__ __forceinline__ unsigned long long pack2(float w) {
    unsigned long long r;
    asm("mov.b64 %0, {%1, %1};" : "=l"(r) : "f"(w));
    return r;
}
__device__ __forceinline__ void fma2(unsigned long long& d,
                                     unsigned long long a,
                                     unsigned long long b) {
    asm("fma.rn.f32x2 %0, %1, %2, %0;" : "+l"(d) : "l"(a), "l"(b));
}
__device__ __forceinline__ float2 unpack2(unsigned long long v) {
    float2 r;
    asm("mov.b64 {%0, %1}, %2;" : "=f"(r.x), "=f"(r.y) : "l"(v));
    return r;
}

// ---------------- Kernel 1: h = X @ W  (8192x256 @ 256x64) ----------------
__global__ __launch_bounds__(256) void k_gemm_h(const float* __restrict__ X,
                                                const float* __restrict__ W) {
    __shared__ __align__(16) float Xs[64 * 68];   // padded: stride 68 avoids bank conflicts
    __shared__ __align__(16) float Ws[64 * 64];
    const int t  = threadIdx.x;
    const int rb = blockIdx.x * 64;
    const int r  = t >> 2;          // 0..63 row within tile
    const int q  = t & 3;           // col group: 16 cols each

    float acc[16];
#pragma unroll
    for (int i = 0; i < 16; i++) acc[i] = 0.f;

    for (int kc = 0; kc < FEAT; kc += 64) {
#pragma unroll
        for (int k = 0; k < 4; k++) {
            int p = t + 256 * k;
            int row = p >> 4, c4 = p & 15;
            float4 v = *(const float4*)&X[(size_t)(rb + row) * FEAT + kc + c4 * 4];
            *(float4*)&Xs[row * 68 + c4 * 4] = v;
        }
#pragma unroll
        for (int k = 0; k < 4; k++) {
            int p = t + 256 * k;
            int row = p >> 4, c4 = p & 15;
            float4 v = *(const float4*)&W[(size_t)(kc + row) * HIDD + c4 * 4];
            *(float4*)&Ws[row * 64 + c4 * 4] = v;
        }
        __syncthreads();
#pragma unroll 16
        for (int k = 0; k < 64; k++) {
            float x = Xs[r * 68 + k];
#pragma unroll
            for (int g = 0; g < 4; g++) {
                float4 wv = *(const float4*)&Ws[k * 64 + q * 16 + g * 4];
                acc[g * 4 + 0] = fmaf(x, wv.x, acc[g * 4 + 0]);
                acc[g * 4 + 1] = fmaf(x, wv.y, acc[g * 4 + 1]);
                acc[g * 4 + 2] = fmaf(x, wv.z, acc[g * 4 + 2]);
                acc[g * 4 + 3] = fmaf(x, wv.w, acc[g * 4 + 3]);
            }
        }
        __syncthreads();
    }
#pragma unroll
    for (int g = 0; g < 4; g++) {
        *(float4*)&g_h[(size_t)(rb + r) * HIDD + q * 16 + g * 4] =
            make_float4(acc[g * 4], acc[g * 4 + 1], acc[g * 4 + 2], acc[g * 4 + 3]);
    }
}

// ---------------- Kernel 2: s_src/s_dst = h . a[:H] / h . a[H:] ----------------
__global__ __launch_bounds__(256) void k_s(const float* __restrict__ a) {
    const int warp = threadIdx.x >> 5, lane = threadIdx.x & 31;
    const int row = blockIdx.x * 8 + warp;
    float h0 = g_h[(size_t)row * HIDD + lane];
    float h1 = g_h[(size_t)row * HIDD + 32 + lane];
    float ps = h0 * a[lane] + h1 * a[32 + lane];
    float pd = h0 * a[64 + lane] + h1 * a[96 + lane];
#pragma unroll
    for (int o = 16; o; o >>= 1) {
        ps += __shfl_xor_sync(0xffffffffu, ps, o);
        pd += __shfl_xor_sync(0xffffffffu, pd, o);
    }
    if (lane == 0) { g_ssrc[row] = ps; g_sdst[row] = pd; }
}

// ---------------- Kernel 3: fused mask + exp + weighted aggregation ----------------
// Softmax without max-shift (|e| bounded, exp stays finite in fp32):
//   l_i   = sum_j adj_ij * exp(leaky(s_i + s_j))
//   acc_i = sum_j adj_ij * exp(leaky(s_i + s_j)) * h_j
// One pass over adj (read exactly once, 256 MB).
__global__ __launch_bounds__(256, 4) void k_main(const int* __restrict__ adj) {
    __shared__ __align__(16) float hs[64 * 64];   // h tile, [j][d]
    __shared__ float ws[64 * 65];                 // w tile, padded stride 65
    __shared__ float ssrc_s[64];

    const int t  = threadIdx.x;
    const int ti = t >> 4;        // 0..15 -> rows ti*4..ti*4+3
    const int td = t & 15;        // 0..15 -> dims/cols td*4..td*4+3
    const int rb = blockIdx.x * 64;
    const int split = blockIdx.y;
    const int j0 = split * JCHUNK;

    if (t < 64) ssrc_s[t] = g_ssrc[rb + t];
    __syncthreads();

    unsigned long long acc[4][2];
#pragma unroll
    for (int a0 = 0; a0 < 4; a0++) { acc[a0][0] = 0ull; acc[a0][1] = 0ull; }
    float lp[4] = {0.f, 0.f, 0.f, 0.f};

    for (int jb = j0; jb < j0 + JCHUNK; jb += 64) {
        // stage h tile (L2-resident, 16 KB)
#pragma unroll
        for (int k = 0; k < 4; k++) {
            int p = t + 256 * k;
            int row = p >> 4, c4 = p & 15;
            *(float4*)&hs[row * 64 + c4 * 4] =
                *(const float4*)&g_h[(size_t)(jb + row) * HIDD + c4 * 4];
        }
        // compute 4x4 weight block
        float4 sd = *(const float4*)&g_sdst[jb + td * 4];
        float sdv[4] = {sd.x, sd.y, sd.z, sd.w};
#pragma unroll
        for (int a0 = 0; a0 < 4; a0++) {
            const int i = ti * 4 + a0;
            int4 av = *(const int4*)&adj[(size_t)(rb + i) * NV + jb + td * 4];
            int am[4] = {av.x, av.y, av.z, av.w};
            float ss = ssrc_s[i];
#pragma unroll
            for (int b = 0; b < 4; b++) {
                float e = ss + sdv[b];
                e = e > 0.f ? e : ALPHA_S * e;
                float w = (am[b] > 0) ? __expf(e) : 0.f;
                ws[i * 65 + td * 4 + b] = w;
                lp[a0] += w;
            }
        }
        __syncthreads();
        // aggregation: acc[4 rows][4 dims] += w * h, packed f32x2
#pragma unroll 16
        for (int jj = 0; jj < 64; jj++) {
            ulonglong2 hv = *(const ulonglong2*)&hs[jj * 64 + td * 4];
#pragma unroll
            for (int a0 = 0; a0 < 4; a0++) {
                unsigned long long w2 = pack2(ws[(ti * 4 + a0) * 65 + jj]);
                fma2(acc[a0][0], w2, hv.x);
                fma2(acc[a0][1], w2, hv.y);
            }
        }
        __syncthreads();
    }

    // write partial accumulators
#pragma unroll
    for (int a0 = 0; a0 < 4; a0++) {
        float2 lo = unpack2(acc[a0][0]);
        float2 hi = unpack2(acc[a0][1]);
        *(float4*)&g_acc[split][(size_t)(rb + ti * 4 + a0) * HIDD + td * 4] =
            make_float4(lo.x, lo.y, hi.x, hi.y);
    }
    // reduce per-row l across the 16 td-threads (reuse ws)
#pragma unroll
    for (int a0 = 0; a0 < 4; a0++) ws[(ti * 4 + a0) * 65 + td] = lp[a0];
    __syncthreads();
    if (t < 64) {
        float s = 0.f;
#pragma unroll
        for (int k = 0; k < 16; k++) s += ws[t * 65 + k];
        g_l[split][rb + t] = s;
    }
}

// ---------------- Kernel 4: out = relu( (sum_s acc) / (sum_s l) ) ----------------
__global__ __launch_bounds__(256) void k_final(float* __restrict__ out) {
    int idx = blockIdx.x * 256 + threadIdx.x;
    if (idx >= NV * HIDD) return;
    int row = idx >> 6;
    float l = g_l[0][row] + g_l[1][row] + g_l[2][row] + g_l[3][row];
    float v = (g_acc[0][idx] + g_acc[1][idx] + g_acc[2][idx] + g_acc[3][idx]) / l;
    out[idx] = v > 0.f ? v : 0.f;
}

extern "C" void kernel_launch(void* const* d_in, const int* in_sizes, int n_in,
                              void* d_out, int out_size) {
    const float* X   = (const float*)d_in[0];      // inputs [N, FEAT]
    const int*   adj = (const int*)  d_in[1];      // adj [N, N]
    // d_in[2] tree_attention: unused by reference
    const float* W   = (const float*)d_in[3];      // W [FEAT, HID]
    const float* a   = (const float*)d_in[4];      // a [2*HID, 1]
    float* out = (float*)d_out;

    k_gemm_h<<<NV / 64, 256>>>(X, W);
    k_s<<<NV / 8, 256>>>(a);
    k_main<<<dim3(NV / 64, JSPLIT), 256>>>(adj);
    k_final<<<(NV * HIDD + 255) / 256, 256>>>(out);
}

// round 13
// speedup vs baseline: 1.8352x; 1.8352x over previous
#include <cuda_runtime.h>
#include <cstdint>

#define NV      8192
#define FEAT    256
#define HIDD    64
#define ALPHA_S 0.2f
#define JSPLIT  8
#define JCHUNK  (NV / JSPLIT)     // 1024
#define JTILE   32
#define M_TILE  128

// ---------------- device scratch (no allocation allowed) ----------------
__device__ float g_h[NV * HIDD];
__device__ float g_ssrc[NV];
__device__ float g_sdst[NV];
__device__ float g_acc[JSPLIT][NV * HIDD];
__device__ float g_l[JSPLIT][NV];

// ---------------- helpers ----------------
__device__ __forceinline__ uint32_t tf32_rna(float x) {
    uint32_t r;
    asm("cvt.rna.tf32.f32 %0, %1;" : "=r"(r) : "f"(x));
    return r;
}

// m16n8k8 tf32 HMMA (baseline PTX, sm_80+; NOT an 'a'-gated feature)
__device__ __forceinline__ void mma_tf32(float* d, const uint32_t* a,
                                         uint32_t b0, uint32_t b1) {
    asm volatile(
        "mma.sync.aligned.m16n8k8.row.col.f32.tf32.tf32.f32 "
        "{%0,%1,%2,%3}, {%4,%5,%6,%7}, {%8,%9}, {%0,%1,%2,%3};"
        : "+f"(d[0]), "+f"(d[1]), "+f"(d[2]), "+f"(d[3])
        : "r"(a[0]), "r"(a[1]), "r"(a[2]), "r"(a[3]), "r"(b0), "r"(b1));
}

// ---------------- Kernel 1: h = X @ W  (8192x256 @ 256x64) ----------------
__global__ __launch_bounds__(256) void k_gemm_h(const float* __restrict__ X,
                                                const float* __restrict__ W) {
    __shared__ __align__(16) float Xs[64 * 68];
    __shared__ __align__(16) float Ws[64 * 64];
    const int t  = threadIdx.x;
    const int rb = blockIdx.x * 64;
    const int r  = t >> 2;
    const int q  = t & 3;

    float acc[16];
#pragma unroll
    for (int i = 0; i < 16; i++) acc[i] = 0.f;

    for (int kc = 0; kc < FEAT; kc += 64) {
#pragma unroll
        for (int k = 0; k < 4; k++) {
            int p = t + 256 * k, row = p >> 4, c4 = p & 15;
            *(float4*)&Xs[row * 68 + c4 * 4] =
                *(const float4*)&X[(size_t)(rb + row) * FEAT + kc + c4 * 4];
        }
#pragma unroll
        for (int k = 0; k < 4; k++) {
            int p = t + 256 * k, row = p >> 4, c4 = p & 15;
            *(float4*)&Ws[row * 64 + c4 * 4] =
                *(const float4*)&W[(size_t)(kc + row) * HIDD + c4 * 4];
        }
        __syncthreads();
#pragma unroll 16
        for (int k = 0; k < 64; k++) {
            float x = Xs[r * 68 + k];
#pragma unroll
            for (int g = 0; g < 4; g++) {
                float4 wv = *(const float4*)&Ws[k * 64 + q * 16 + g * 4];
                acc[g * 4 + 0] = fmaf(x, wv.x, acc[g * 4 + 0]);
                acc[g * 4 + 1] = fmaf(x, wv.y, acc[g * 4 + 1]);
                acc[g * 4 + 2] = fmaf(x, wv.z, acc[g * 4 + 2]);
                acc[g * 4 + 3] = fmaf(x, wv.w, acc[g * 4 + 3]);
            }
        }
        __syncthreads();
    }
#pragma unroll
    for (int g = 0; g < 4; g++)
        *(float4*)&g_h[(size_t)(rb + r) * HIDD + q * 16 + g * 4] =
            make_float4(acc[g * 4], acc[g * 4 + 1], acc[g * 4 + 2], acc[g * 4 + 3]);
}

// ---------------- Kernel 2: s_src / s_dst ----------------
__global__ __launch_bounds__(256) void k_s(const float* __restrict__ a) {
    const int warp = threadIdx.x >> 5, lane = threadIdx.x & 31;
    const int row = blockIdx.x * 8 + warp;
    float h0 = g_h[(size_t)row * HIDD + lane];
    float h1 = g_h[(size_t)row * HIDD + 32 + lane];
    float ps = h0 * a[lane] + h1 * a[32 + lane];
    float pd = h0 * a[64 + lane] + h1 * a[96 + lane];
#pragma unroll
    for (int o = 16; o; o >>= 1) {
        ps += __shfl_xor_sync(0xffffffffu, ps, o);
        pd += __shfl_xor_sync(0xffffffffu, pd, o);
    }
    if (lane == 0) { g_ssrc[row] = ps; g_sdst[row] = pd; }
}

// ---------------- Kernel 3: fused w-phase + tf32 mma.sync aggregation ----------------
// Per block: 128 threads / 4 warps, M_TILE=128 i-rows, JCHUNK j columns.
// acc[i][d] += sum_j w[i][j] * h[j][d], w = adj ? exp(leaky(s_i+s_j)) : 0 (tf32-rounded).
// Strides chosen for conflict-free fragment LDS:
//   w_s stride 36: bank(g,c) = (g*36 + c) % 32 = g*4 + c  -> 32 distinct
//   h_s stride 72: bank(c,g) = (c*72 + g) % 32 = c*8 + g  -> 32 distinct
__global__ __launch_bounds__(128, 4) void k_main(const int* __restrict__ adj) {
    __shared__ __align__(16) uint32_t h_s[JTILE][72];   // tf32 bits, [j][d]
    __shared__ __align__(16) uint32_t w_s[M_TILE][36];  // tf32 bits, [i][j]

    const int t = threadIdx.x, lane = t & 31, warp = t >> 5;
    const int g = lane >> 2, c = lane & 3;
    const int rb = blockIdx.x * M_TILE;
    const int split = blockIdx.y;
    const int j0 = split * JCHUNK;

    // w-phase mapping: thread handles i in {ih, 64+ih}, j-half jh (16 cols)
    const int ih = t >> 1;
    const int jh = t & 1;
    const float ss0 = g_ssrc[rb + ih];
    const float ss1 = g_ssrc[rb + 64 + ih];
    float lp0 = 0.f, lp1 = 0.f;

    const int* arow0 = adj + (size_t)(rb + ih) * NV + j0 + jh * 16;
    const int* arow1 = arow0 + (size_t)64 * NV;

    float C[2][8][4];
#pragma unroll
    for (int mb = 0; mb < 2; mb++)
#pragma unroll
        for (int nb = 0; nb < 8; nb++)
#pragma unroll
            for (int k = 0; k < 4; k++) C[mb][nb][k] = 0.f;

    // staging mapping for h tile
    const int hr = t >> 2;       // 0..31 (j row)
    const int hq = t & 3;        // d quarter

    for (int it = 0; it < JCHUNK / JTILE; ++it) {
        const int jb = j0 + it * JTILE;

        // ---- stage h tile [32 j][64 d] as tf32 ----
        {
            const float* src = &g_h[(size_t)(jb + hr) * HIDD + hq * 16];
#pragma unroll
            for (int k = 0; k < 4; k++) {
                float4 v = *(const float4*)(src + k * 4);
                uint4 u = make_uint4(tf32_rna(v.x), tf32_rna(v.y),
                                     tf32_rna(v.z), tf32_rna(v.w));
                *(uint4*)&h_s[hr][hq * 16 + k * 4] = u;
            }
        }

        // ---- w tile [128 i][32 j], tf32-rounded; denom uses identical bits ----
        {
            const float* sdp = &g_sdst[jb + jh * 16];
#pragma unroll
            for (int half = 0; half < 2; half++) {
                const int* ar = (half ? arow1 : arow0) + it * JTILE;
                const float ss = half ? ss1 : ss0;
                float lpl = 0.f;
                uint32_t* wrow = &w_s[half * 64 + ih][jh * 16];
#pragma unroll
                for (int q = 0; q < 4; q++) {
                    int4 av = *(const int4*)(ar + q * 4);
                    float4 sd = *(const float4*)(sdp + q * 4);
                    float ev[4] = {ss + sd.x, ss + sd.y, ss + sd.z, ss + sd.w};
                    int am[4] = {av.x, av.y, av.z, av.w};
                    uint4 wu;
                    uint32_t* wp = &wu.x;
#pragma unroll
                    for (int b = 0; b < 4; b++) {
                        float e = fmaxf(ev[b], ALPHA_S * ev[b]);   // leaky relu
                        float w = (am[b] > 0) ? __expf(e) : 0.f;
                        uint32_t wt = tf32_rna(w);
                        wp[b] = wt;
                        lpl += __uint_as_float(wt);
                    }
                    *(uint4*)(wrow + q * 4) = wu;
                }
                if (half) lp1 += lpl; else lp0 += lpl;
            }
        }
        __syncthreads();

        // ---- mma: C[32 i][64 d] += w[32,32] x h[32,64] per warp ----
        const int i0 = warp * 32;
#pragma unroll
        for (int kc = 0; kc < 4; kc++) {
            const int jc = kc * 8;
            uint32_t a[2][4];
#pragma unroll
            for (int mb = 0; mb < 2; mb++) {
                a[mb][0] = w_s[i0 + mb * 16 + g][jc + c];
                a[mb][1] = w_s[i0 + mb * 16 + 8 + g][jc + c];
                a[mb][2] = w_s[i0 + mb * 16 + g][jc + c + 4];
                a[mb][3] = w_s[i0 + mb * 16 + 8 + g][jc + c + 4];
            }
#pragma unroll
            for (int nb = 0; nb < 8; nb++) {
                uint32_t b0 = h_s[jc + c][nb * 8 + g];
                uint32_t b1 = h_s[jc + c + 4][nb * 8 + g];
                mma_tf32(C[0][nb], a[0], b0, b1);
                mma_tf32(C[1][nb], a[1], b0, b1);
            }
        }
        __syncthreads();
    }

    // ---- epilogue: C regs -> g_acc ----
#pragma unroll
    for (int mb = 0; mb < 2; mb++)
#pragma unroll
        for (int hrow = 0; hrow < 2; hrow++) {
            const int i = rb + warp * 32 + mb * 16 + hrow * 8 + g;
            float* dst = &g_acc[split][(size_t)i * HIDD + c * 2];
#pragma unroll
            for (int nb = 0; nb < 8; nb++)
                *(float2*)(dst + nb * 8) =
                    make_float2(C[mb][nb][hrow * 2 + 0], C[mb][nb][hrow * 2 + 1]);
        }

    // ---- denominators: combine the two jh halves (adjacent lanes) ----
    float o0 = __shfl_xor_sync(0xffffffffu, lp0, 1);
    float o1 = __shfl_xor_sync(0xffffffffu, lp1, 1);
    if (jh == 0) {
        g_l[split][rb + ih]      = lp0 + o0;
        g_l[split][rb + 64 + ih] = lp1 + o1;
    }
}

// ---------------- Kernel 4: out = relu( sum acc / sum l ) ----------------
__global__ __launch_bounds__(256) void k_final(float* __restrict__ out) {
    int idx = blockIdx.x * 256 + threadIdx.x;
    if (idx >= NV * HIDD) return;
    int row = idx >> 6;
    float l = 0.f, v = 0.f;
#pragma unroll
    for (int s = 0; s < JSPLIT; s++) {
        l += g_l[s][row];
        v += g_acc[s][idx];
    }
    v /= l;
    out[idx] = v > 0.f ? v : 0.f;
}

extern "C" void kernel_launch(void* const* d_in, const int* in_sizes, int n_in,
                              void* d_out, int out_size) {
    const float* X   = (const float*)d_in[0];
    const int*   adj = (const int*)  d_in[1];
    const float* W   = (const float*)d_in[3];
    const float* a   = (const float*)d_in[4];
    float* out = (float*)d_out;

    k_gemm_h<<<NV / 64, 256>>>(X, W);
    k_s<<<NV / 8, 256>>>(a);
    k_main<<<dim3(NV / M_TILE, JSPLIT), 128>>>(adj);
    k_final<<<(NV * HIDD + 255) / 256, 256>>>(out);
}